// round 1
// baseline (speedup 1.0000x reference)
#include <cuda_runtime.h>
#include <math.h>

#define NATOMS 500000
#define NBATCH 1024

static const int h_counts[7] = {20000,80000,150000,150000,75000,20000,5000};
static const int h_offs[7]   = {0,20000,100000,250000,400000,475000};
// note: full offsets
static const int h_offs_full[7] = {0,20000,100000,250000,400000,475000,495000};

// ---- scratch (device globals: no runtime allocation allowed) ----
__device__ float g_h1[(size_t)NATOMS*64];
__device__ float g_h2[(size_t)NATOMS*64];
__device__ float g_p [(size_t)NATOMS*128];
__device__ int   g_cnt[NBATCH];
__device__ int   g_off[NBATCH+1];
__device__ int   g_cur[NBATCH];
__device__ int   g_sorted[NATOMS];

// ============================================================
// Fused graph-conv: gather(self + neighbor-sum) -> dual GEMM ->
// +bias -> tanh -> batchnorm.  One launch per degree segment.
// Tile: 64 atoms x 64 cols, 256 threads, 4x4 register micro-tile.
// ============================================================
template<int FIN>
__global__ __launch_bounds__(256) void gc_kernel(
    const float* __restrict__ feat,            // full N x FIN
    const int*   __restrict__ adj,             // cnt x d (null if d==0)
    int d, int cnt, int gbase,
    const float* __restrict__ Wn,              // FIN x 64 (this degree)
    const float* __restrict__ Ws,              // FIN x 64 (this degree)
    const float* __restrict__ bias,            // 64
    const float* __restrict__ bng, const float* __restrict__ bnb,
    const float* __restrict__ bnm, const float* __restrict__ bnv,
    float* __restrict__ out)                   // full N x 64
{
    constexpr int XSTR = FIN + 1;
    extern __shared__ float sm[];
    float* s_ws = sm;                          // FIN*64
    float* s_wn = s_ws + FIN*64;               // FIN*64
    float* s_xs = s_wn + FIN*64;               // 64*XSTR
    float* s_xn = s_xs + 64*XSTR;              // 64*XSTR
    float* s_sc = s_xn + 64*XSTR;              // 64
    float* s_sh = s_sc + 64;                   // 64
    float* s_b  = s_sh + 64;                   // 64

    const int tid = threadIdx.x;

    for (int i = tid; i < FIN*64; i += 256) s_ws[i] = Ws[i];
    if (d > 0)
        for (int i = tid; i < FIN*64; i += 256) s_wn[i] = Wn[i];
    if (tid < 64) {
        float s = bng[tid] * rsqrtf(bnv[tid] + 1e-3f);
        s_sc[tid] = s;
        s_sh[tid] = bnb[tid] - bnm[tid]*s;
        s_b[tid]  = bias[tid];
    }

    const int tile0 = blockIdx.x * 64;   // local atom base within segment
    const int wid  = tid >> 5;
    const int lane = tid & 31;

    // ---- gather phase: one warp owns atoms wid, wid+8, ... ----
    for (int a = wid; a < 64; a += 8) {
        int la = tile0 + a;
        float fs[3] = {0.f,0.f,0.f};
        float fn[3] = {0.f,0.f,0.f};
        if (la < cnt) {
            const float* row = feat + (size_t)(gbase + la) * FIN;
            #pragma unroll
            for (int r = 0; r < 3; r++) {
                int k = lane + 32*r;
                if (k < FIN) fs[r] = row[k];
            }
            for (int j = 0; j < d; j++) {
                int nb = adj[(size_t)la * d + j];
                const float* nr = feat + (size_t)nb * FIN;
                #pragma unroll
                for (int r = 0; r < 3; r++) {
                    int k = lane + 32*r;
                    if (k < FIN) fn[r] += nr[k];
                }
            }
        }
        #pragma unroll
        for (int r = 0; r < 3; r++) {
            int k = lane + 32*r;
            if (k < FIN) {
                s_xs[a*XSTR + k] = fs[r];
                s_xn[a*XSTR + k] = fn[r];
            }
        }
    }
    __syncthreads();

    // ---- GEMM phase ----
    const int ty = tid >> 4;    // 0..15 -> 4 atoms each
    const int tx = tid & 15;    // 0..15 -> 4 cols each
    float acc[4][4] = {};

    if (d > 0) {
        #pragma unroll 4
        for (int k = 0; k < FIN; k++) {
            float4 w4  = *reinterpret_cast<const float4*>(&s_ws[k*64 + (tx<<2)]);
            float4 wn4 = *reinterpret_cast<const float4*>(&s_wn[k*64 + (tx<<2)]);
            #pragma unroll
            for (int i = 0; i < 4; i++) {
                float xs = s_xs[(ty*4+i)*XSTR + k];
                float xn = s_xn[(ty*4+i)*XSTR + k];
                acc[i][0] += xs*w4.x + xn*wn4.x;
                acc[i][1] += xs*w4.y + xn*wn4.y;
                acc[i][2] += xs*w4.z + xn*wn4.z;
                acc[i][3] += xs*w4.w + xn*wn4.w;
            }
        }
    } else {
        #pragma unroll 4
        for (int k = 0; k < FIN; k++) {
            float4 w4 = *reinterpret_cast<const float4*>(&s_ws[k*64 + (tx<<2)]);
            #pragma unroll
            for (int i = 0; i < 4; i++) {
                float xs = s_xs[(ty*4+i)*XSTR + k];
                acc[i][0] += xs*w4.x;
                acc[i][1] += xs*w4.y;
                acc[i][2] += xs*w4.z;
                acc[i][3] += xs*w4.w;
            }
        }
    }

    // ---- epilogue: bias -> tanh -> bn -> store ----
    const int c0 = tx << 2;
    #pragma unroll
    for (int i = 0; i < 4; i++) {
        int la = tile0 + ty*4 + i;
        if (la < cnt) {
            float4 o;
            o.x = tanhf(acc[i][0] + s_b[c0+0]) * s_sc[c0+0] + s_sh[c0+0];
            o.y = tanhf(acc[i][1] + s_b[c0+1]) * s_sc[c0+1] + s_sh[c0+1];
            o.z = tanhf(acc[i][2] + s_b[c0+2]) * s_sc[c0+2] + s_sh[c0+2];
            o.w = tanhf(acc[i][3] + s_b[c0+3]) * s_sc[c0+3] + s_sh[c0+3];
            *reinterpret_cast<float4*>(&out[(size_t)(gbase + la)*64 + c0]) = o;
        }
    }
}

// ============================================================
// graph_pool: out[a] = max(self, neighbors) elementwise (64 ch).
// One warp per atom, float2 per lane. d==0 -> copy.
// ============================================================
__global__ __launch_bounds__(256) void pool_kernel(
    const float* __restrict__ in, const int* __restrict__ adj,
    int d, int cnt, int gbase, float* __restrict__ out)
{
    int wg   = (blockIdx.x * blockDim.x + threadIdx.x) >> 5;
    int lane = threadIdx.x & 31;
    if (wg >= cnt) return;
    const float2* self = reinterpret_cast<const float2*>(in + (size_t)(gbase + wg)*64);
    float2 m = self[lane];
    for (int j = 0; j < d; j++) {
        int nb = adj[(size_t)wg * d + j];
        float2 v = reinterpret_cast<const float2*>(in + (size_t)nb*64)[lane];
        m.x = fmaxf(m.x, v.x);
        m.y = fmaxf(m.y, v.y);
    }
    reinterpret_cast<float2*>(out + (size_t)(gbase + wg)*64)[lane] = m;
}

// ============================================================
// d1: dense GEMM (N x 64) @ (64 x 128) + bias -> tanh -> bn3 -> p
// Tile 64 atoms x 128 cols, 256 threads, 8 atoms x 4 cols per thread.
// ============================================================
__global__ __launch_bounds__(256) void d1_kernel(
    const float* __restrict__ in,      // N x 64
    const float* __restrict__ W,       // 64 x 128
    const float* __restrict__ b,       // 128
    const float* __restrict__ bng, const float* __restrict__ bnb,
    const float* __restrict__ bnm, const float* __restrict__ bnv,
    float* __restrict__ out)           // N x 128
{
    extern __shared__ float sm[];
    float* s_w  = sm;                 // 64*128
    float* s_x  = s_w + 64*128;       // 64*65
    float* s_sc = s_x + 64*65;        // 128
    float* s_sh = s_sc + 128;         // 128
    float* s_b  = s_sh + 128;         // 128

    const int tid = threadIdx.x;
    for (int i = tid; i < 64*128; i += 256) s_w[i] = W[i];
    if (tid < 128) {
        float s = bng[tid] * rsqrtf(bnv[tid] + 1e-3f);
        s_sc[tid] = s;
        s_sh[tid] = bnb[tid] - bnm[tid]*s;
        s_b[tid]  = b[tid];
    }
    const int tile0 = blockIdx.x * 64;
    for (int i = tid; i < 64*64; i += 256) {
        int a = i >> 6, k = i & 63;
        int la = tile0 + a;
        s_x[a*65 + k] = (la < NATOMS) ? in[(size_t)la*64 + k] : 0.f;
    }
    __syncthreads();

    const int tx = tid & 31;   // 32 col-quads -> 128 cols
    const int ty = tid >> 5;   // 8 groups -> 8 atoms each
    float acc[8][4] = {};
    #pragma unroll 4
    for (int k = 0; k < 64; k++) {
        float4 w4 = *reinterpret_cast<const float4*>(&s_w[k*128 + (tx<<2)]);
        #pragma unroll
        for (int i = 0; i < 8; i++) {
            float x = s_x[(ty*8+i)*65 + k];
            acc[i][0] += x*w4.x;
            acc[i][1] += x*w4.y;
            acc[i][2] += x*w4.z;
            acc[i][3] += x*w4.w;
        }
    }
    const int c0 = tx << 2;
    #pragma unroll
    for (int i = 0; i < 8; i++) {
        int la = tile0 + ty*8 + i;
        if (la < NATOMS) {
            float4 o;
            o.x = tanhf(acc[i][0] + s_b[c0+0]) * s_sc[c0+0] + s_sh[c0+0];
            o.y = tanhf(acc[i][1] + s_b[c0+1]) * s_sc[c0+1] + s_sh[c0+1];
            o.z = tanhf(acc[i][2] + s_b[c0+2]) * s_sc[c0+2] + s_sh[c0+2];
            o.w = tanhf(acc[i][3] + s_b[c0+3]) * s_sc[c0+3] + s_sh[c0+3];
            *reinterpret_cast<float4*>(&out[(size_t)la*128 + c0]) = o;
        }
    }
}

// ============================================================
// counting sort of atoms by membership (for deterministic-layout
// contiguous segment reduction; avoids 128M float atomics)
// ============================================================
__global__ void zero_cnt_kernel() {
    int i = blockIdx.x * blockDim.x + threadIdx.x;
    if (i < NBATCH) g_cnt[i] = 0;
}
__global__ void hist_kernel(const int* __restrict__ mem) {
    int i = blockIdx.x * blockDim.x + threadIdx.x;
    if (i < NATOMS) atomicAdd(&g_cnt[mem[i]], 1);
}
__global__ void scan_kernel() {   // 1 block, 1024 threads
    __shared__ int s[NBATCH];
    int t = threadIdx.x;
    s[t] = g_cnt[t];
    __syncthreads();
    for (int ofs = 1; ofs < NBATCH; ofs <<= 1) {
        int v = (t >= ofs) ? s[t - ofs] : 0;
        __syncthreads();
        s[t] += v;
        __syncthreads();
    }
    g_off[t+1] = s[t];
    if (t == 0) g_off[0] = 0;
    g_cur[t] = s[t] - g_cnt[t];   // exclusive prefix
}
__global__ void scatter_kernel(const int* __restrict__ mem) {
    int i = blockIdx.x * blockDim.x + threadIdx.x;
    if (i < NATOMS) {
        int p = atomicAdd(&g_cur[mem[i]], 1);
        g_sorted[p] = i;
    }
}

// ============================================================
// graph_gather (segment sum + max) -> tanh -> d2+sigmoid -> d3.
// One block per batch segment (128 threads = 128 p-features).
// ============================================================
__global__ __launch_bounds__(128) void reduce_kernel(
    const float* __restrict__ d2W,   // 256 x 64
    const float* __restrict__ d2b,   // 64
    const float* __restrict__ d3W,   // 64
    const float* __restrict__ d3b,   // 1
    float* __restrict__ outp)        // 1024
{
    __shared__ float gs[256];
    __shared__ int   sidx[512];
    __shared__ float ssig[64];
    const int b = blockIdx.x, t = threadIdx.x;
    const int start = g_off[b], end = g_off[b+1];

    float sum = 0.f;
    float mx  = -INFINITY;
    for (int base = start; base < end; base += 512) {
        int n = min(512, end - base);
        for (int i = t; i < n; i += 128) sidx[i] = g_sorted[base + i];
        __syncthreads();
        int i = 0;
        for (; i + 4 <= n; i += 4) {
            float v0 = g_p[(size_t)sidx[i+0]*128 + t];
            float v1 = g_p[(size_t)sidx[i+1]*128 + t];
            float v2 = g_p[(size_t)sidx[i+2]*128 + t];
            float v3 = g_p[(size_t)sidx[i+3]*128 + t];
            sum += (v0 + v1) + (v2 + v3);
            mx = fmaxf(mx, fmaxf(fmaxf(v0, v1), fmaxf(v2, v3)));
        }
        for (; i < n; i++) {
            float v = g_p[(size_t)sidx[i]*128 + t];
            sum += v;
            mx = fmaxf(mx, v);
        }
        __syncthreads();
    }
    gs[t]       = tanhf(sum);
    gs[128 + t] = tanhf(mx);
    __syncthreads();

    if (t < 64) {
        float a = d2b[t];
        #pragma unroll 4
        for (int k = 0; k < 256; k++) a += gs[k] * __ldg(&d2W[k*64 + t]);
        ssig[t] = 1.f / (1.f + expf(-a));
    }
    __syncthreads();
    if (t < 32) {
        float v = ssig[t]*__ldg(&d3W[t]) + ssig[t+32]*__ldg(&d3W[t+32]);
        #pragma unroll
        for (int o = 16; o; o >>= 1) v += __shfl_down_sync(0xffffffffu, v, o);
        if (t == 0) outp[b] = v + d3b[0];
    }
}

// ============================================================
extern "C" void kernel_launch(void* const* d_in, const int* in_sizes, int n_in,
                              void* d_out, int out_size)
{
    const float* feat       = (const float*)d_in[0];
    const int*   membership = (const int*)  d_in[1];
    const int* adj[7];
    adj[0] = nullptr;
    for (int d = 1; d <= 6; d++) adj[d] = (const int*)d_in[1 + d];
    const float* gc1_Wn = (const float*)d_in[8];
    const float* gc1_Ws = (const float*)d_in[9];
    const float* gc1_b  = (const float*)d_in[10];
    const float* gc2_Wn = (const float*)d_in[11];
    const float* gc2_Ws = (const float*)d_in[12];
    const float* gc2_b  = (const float*)d_in[13];
    const float* bn1g = (const float*)d_in[14];
    const float* bn1b = (const float*)d_in[15];
    const float* bn1m = (const float*)d_in[16];
    const float* bn1v = (const float*)d_in[17];
    const float* bn3g = (const float*)d_in[18];
    const float* bn3b = (const float*)d_in[19];
    const float* bn3m = (const float*)d_in[20];
    const float* bn3v = (const float*)d_in[21];
    const float* d1W = (const float*)d_in[22];
    const float* d1b = (const float*)d_in[23];
    const float* d2W = (const float*)d_in[24];
    const float* d2b = (const float*)d_in[25];
    const float* d3W = (const float*)d_in[26];
    const float* d3b = (const float*)d_in[27];

    void* pp;
    cudaGetSymbolAddress(&pp, g_h1); float* h1 = (float*)pp;
    cudaGetSymbolAddress(&pp, g_h2); float* h2 = (float*)pp;
    cudaGetSymbolAddress(&pp, g_p);  float* pf = (float*)pp;

    const int SM75 = (75*64*2 + 64*76*2 + 192) * 4;   // 78080 B
    const int SM64 = (64*64*2 + 64*65*2 + 192) * 4;   // 66816 B
    const int SMD1 = (64*128 + 64*65 + 384) * 4;      // 50944 B
    cudaFuncSetAttribute(gc_kernel<75>, cudaFuncAttributeMaxDynamicSharedMemorySize, SM75);
    cudaFuncSetAttribute(gc_kernel<64>, cudaFuncAttributeMaxDynamicSharedMemorySize, SM64);
    cudaFuncSetAttribute(d1_kernel,     cudaFuncAttributeMaxDynamicSharedMemorySize, SMD1);

    // ---- gc1 + bn1 -> h1 ----
    for (int d = 0; d <= 6; d++) {
        int cnt = h_counts[d], gb = h_offs_full[d];
        int grid = (cnt + 63) / 64;
        gc_kernel<75><<<grid, 256, SM75>>>(
            feat, adj[d], d, cnt, gb,
            d ? gc1_Wn + (size_t)(d-1)*75*64 : gc1_Wn,
            gc1_Ws + (size_t)d*75*64, gc1_b + d*64,
            bn1g, bn1b, bn1m, bn1v, h1);
    }
    // ---- pool1: h1 -> h2 ----
    for (int d = 0; d <= 6; d++) {
        int cnt = h_counts[d], gb = h_offs_full[d];
        int grid = (cnt*32 + 255) / 256;
        pool_kernel<<<grid, 256>>>(h1, adj[d], d, cnt, gb, h2);
    }
    // ---- gc2 + bn1 -> h1 ----
    for (int d = 0; d <= 6; d++) {
        int cnt = h_counts[d], gb = h_offs_full[d];
        int grid = (cnt + 63) / 64;
        gc_kernel<64><<<grid, 256, SM64>>>(
            h2, adj[d], d, cnt, gb,
            d ? gc2_Wn + (size_t)(d-1)*64*64 : gc2_Wn,
            gc2_Ws + (size_t)d*64*64, gc2_b + d*64,
            bn1g, bn1b, bn1m, bn1v, h1);
    }
    // ---- pool2: h1 -> h2 ----
    for (int d = 0; d <= 6; d++) {
        int cnt = h_counts[d], gb = h_offs_full[d];
        int grid = (cnt*32 + 255) / 256;
        pool_kernel<<<grid, 256>>>(h1, adj[d], d, cnt, gb, h2);
    }
    // ---- d1 + tanh + bn3 -> p ----
    d1_kernel<<<(NATOMS + 63)/64, 256, SMD1>>>(h2, d1W, d1b, bn3g, bn3b, bn3m, bn3v, pf);

    // ---- counting sort by membership ----
    zero_cnt_kernel<<<(NBATCH + 255)/256, 256>>>();
    hist_kernel<<<(NATOMS + 255)/256, 256>>>(membership);
    scan_kernel<<<1, 1024>>>();
    scatter_kernel<<<(NATOMS + 255)/256, 256>>>(membership);

    // ---- segment reduce + final MLP -> out ----
    reduce_kernel<<<NBATCH, 128>>>(d2W, d2b, d3W, d3b, (float*)d_out);
}